// round 7
// baseline (speedup 1.0000x reference)
#include <cuda_runtime.h>
#include <math.h>

// Problem constants (fixed shapes from reference)
#define DMODEL 1024
#define NHEADS 16
#define DK     64
#define BATCH  2
#define SEQ    2048
#define MROWS  (BATCH*SEQ)   // 4096

// Scratch (device globals; no allocation allowed)
__device__ float g_Qh[BATCH*NHEADS*SEQ*DK];   // [B][H][S][dk], Q pre-scaled by 1/sqrt(dk)
__device__ float g_Kh[BATCH*NHEADS*SEQ*DK];
__device__ float g_Vh[BATCH*NHEADS*SEQ*DK];
__device__ float g_ctx[BATCH*SEQ*DMODEL];     // [B][S][H*dk]

// ---------------------------------------------------------------------------
// GEMM: C = (A[M,K] @ W[K,N] + bias) * scale   (unchanged from R2 — at roofline)
// ---------------------------------------------------------------------------
template <int HEAD_MODE>
__global__ __launch_bounds__(256)
void gemm_bias_kernel(const float* __restrict__ A,
                      const float* __restrict__ W,
                      const float* __restrict__ bias,
                      float* __restrict__ C,
                      float scale)
{
    constexpr int N = DMODEL, K = DMODEL;
    constexpr int BM = 128, BN = 128, BK = 16;

    __shared__ float As[BK][BM];
    __shared__ float Ws[BK][BN];

    const int tid = threadIdx.x;
    const int tx  = tid & 15;
    const int ty  = tid >> 4;
    const int mbase = blockIdx.y * BM;
    const int nbase = blockIdx.x * BN;

    const int a_row = tid >> 2;
    const int a_c4  = tid & 3;
    const int w_k  = tid >> 5;
    const int w_n4 = tid & 31;

    float acc[8][8];
#pragma unroll
    for (int i = 0; i < 8; ++i)
#pragma unroll
        for (int j = 0; j < 8; ++j) acc[i][j] = 0.0f;

    for (int k0 = 0; k0 < K; k0 += BK) {
        __syncthreads();
#pragma unroll
        for (int r = 0; r < 2; ++r) {
            int row = a_row + 64 * r;
            float4 v = *(const float4*)&A[(size_t)(mbase + row) * K + k0 + a_c4 * 4];
            As[a_c4 * 4 + 0][row] = v.x;
            As[a_c4 * 4 + 1][row] = v.y;
            As[a_c4 * 4 + 2][row] = v.z;
            As[a_c4 * 4 + 3][row] = v.w;
        }
#pragma unroll
        for (int r = 0; r < 2; ++r) {
            int kk = w_k + 8 * r;
            float4 v = *(const float4*)&W[(size_t)(k0 + kk) * N + nbase + w_n4 * 4];
            *(float4*)&Ws[kk][w_n4 * 4] = v;
        }
        __syncthreads();

#pragma unroll
        for (int kk = 0; kk < BK; ++kk) {
            float a[8], w[8];
            *(float4*)&a[0] = *(const float4*)&As[kk][ty * 8];
            *(float4*)&a[4] = *(const float4*)&As[kk][ty * 8 + 4];
            *(float4*)&w[0] = *(const float4*)&Ws[kk][tx * 8];
            *(float4*)&w[4] = *(const float4*)&Ws[kk][tx * 8 + 4];
#pragma unroll
            for (int i = 0; i < 8; ++i)
#pragma unroll
                for (int j = 0; j < 8; ++j)
                    acc[i][j] += a[i] * w[j];
        }
    }

    const int ncol0 = nbase + tx * 8;
    float bv[8];
#pragma unroll
    for (int j = 0; j < 8; ++j) bv[j] = bias[ncol0 + j];

#pragma unroll
    for (int i = 0; i < 8; ++i) {
        int m = mbase + ty * 8 + i;
        float out[8];
#pragma unroll
        for (int j = 0; j < 8; ++j) out[j] = (acc[i][j] + bv[j]) * scale;

        if (HEAD_MODE) {
            int b = m >> 11;
            int s = m & 2047;
            int h = ncol0 >> 6;
            int d = ncol0 & 63;
            float* dst = &C[(((size_t)(b * NHEADS + h)) * SEQ + s) * DK + d];
            *(float4*)&dst[0] = make_float4(out[0], out[1], out[2], out[3]);
            *(float4*)&dst[4] = make_float4(out[4], out[5], out[6], out[7]);
        } else {
            float* dst = &C[(size_t)m * N + ncol0];
            *(float4*)&dst[0] = make_float4(out[0], out[1], out[2], out[3]);
            *(float4*)&dst[4] = make_float4(out[4], out[5], out[6], out[7]);
        }
    }
}

// ---------------------------------------------------------------------------
// Flash attention v2: per (b, h, q-tile of 128). 256 threads.
// Tile: 128 q-rows x 128 keys per iteration. Per thread: s[8][8], o[8][4].
// Smem traffic ~1.25 B/FMA (was 2.0) -> fma-bound instead of L1-bound.
// Key ownership per thread (for conflict-free LDS.128): keys {tx*4..tx*4+3}
// and {64+tx*4..64+tx*4+3}. dk ownership for O: {tx*4..tx*4+3}.
// ---------------------------------------------------------------------------
#define BQ   128
#define BKEY 128
#define QST  68    // Qs stride  (64 d + pad)
#define KST  132   // Kt stride  (128 keys + pad)
#define VST  68    // Vs stride  (64 d + pad)
#define PST  132   // Ps stride  (128 keys + pad)
#define ATTN_SMEM ((BQ*QST + DK*KST + BKEY*VST + BQ*PST) * 4)  // 171,008 B

__global__ __launch_bounds__(256)
void attn_kernel(const float* __restrict__ Qh,
                 const float* __restrict__ Kh,
                 const float* __restrict__ Vh,
                 float* __restrict__ ctx)
{
    extern __shared__ float sm[];
    float* Qs = sm;                          // [BQ][QST]
    float* Kt = Qs + BQ * QST;               // [DK][KST]  (Kt[d][key])
    float* Vs = Kt + DK * KST;               // [BKEY][VST]
    float* Ps = Vs + BKEY * VST;             // [BQ][PST]

    const int tid = threadIdx.x;
    const int tx  = tid & 15;    // 16 cols
    const int ty  = tid >> 4;    // 16 row-groups
    const int qt = blockIdx.x;
    const int h  = blockIdx.y;
    const int b  = blockIdx.z;

    const int r0  = ty * 8;      // 8 q rows per thread
    const int c0k = tx * 4;      // first key col (second group at +64)
    const int c0d = tx * 4;      // dk cols for O

    const float* Qbase = Qh + (((size_t)(b * NHEADS + h)) * SEQ + qt * BQ) * DK;
    const float* Kbase = Kh + ((size_t)(b * NHEADS + h)) * SEQ * DK;
    const float* Vbase = Vh + ((size_t)(b * NHEADS + h)) * SEQ * DK;

    // Load Q tile: 128x64 = 2048 float4, 8 per thread
#pragma unroll
    for (int it = 0; it < 8; ++it) {
        int idx = tid + it * 256;
        int row = idx >> 4;
        int d4  = idx & 15;
        float4 v = *(const float4*)&Qbase[row * DK + d4 * 4];
        *(float4*)&Qs[row * QST + d4 * 4] = v;
    }

    float m_i[8], l_i[8], o[8][4];
#pragma unroll
    for (int i = 0; i < 8; ++i) {
        m_i[i] = -INFINITY;
        l_i[i] = 0.0f;
#pragma unroll
        for (int j = 0; j < 4; ++j) o[i][j] = 0.0f;
    }

    for (int kb = 0; kb < SEQ / BKEY; ++kb) {
        __syncthreads();   // protect Kt/Vs/Ps from previous iteration's readers
        // Load K (transposed -> Kt[d][key]) and V (Vs[key][d]); 8 float4 each
#pragma unroll
        for (int it = 0; it < 8; ++it) {
            int idx = tid + it * 256;
            int r  = idx >> 4;      // key within tile: 0..127
            int d4 = idx & 15;
            float4 kv = *(const float4*)&Kbase[(size_t)(kb * BKEY + r) * DK + d4 * 4];
            Kt[(d4 * 4 + 0) * KST + r] = kv.x;
            Kt[(d4 * 4 + 1) * KST + r] = kv.y;
            Kt[(d4 * 4 + 2) * KST + r] = kv.z;
            Kt[(d4 * 4 + 3) * KST + r] = kv.w;
            float4 vv = *(const float4*)&Vbase[(size_t)(kb * BKEY + r) * DK + d4 * 4];
            *(float4*)&Vs[r * VST + d4 * 4] = vv;
        }
        __syncthreads();

        // ---- S = Q @ K^T  (8x8 per thread; Q pre-scaled by 1/sqrt(dk)) ----
        float s[8][8];
#pragma unroll
        for (int i = 0; i < 8; ++i)
#pragma unroll
            for (int j = 0; j < 8; ++j) s[i][j] = 0.0f;

#pragma unroll
        for (int d4 = 0; d4 < 16; ++d4) {
            float a[8][4];
#pragma unroll
            for (int i = 0; i < 8; ++i) {
                float4 q = *(const float4*)&Qs[(r0 + i) * QST + d4 * 4];
                a[i][0] = q.x; a[i][1] = q.y; a[i][2] = q.z; a[i][3] = q.w;
            }
#pragma unroll
            for (int t = 0; t < 4; ++t) {
                float4 k0 = *(const float4*)&Kt[(d4 * 4 + t) * KST + c0k];
                float4 k1 = *(const float4*)&Kt[(d4 * 4 + t) * KST + 64 + c0k];
#pragma unroll
                for (int i = 0; i < 8; ++i) {
                    float av = a[i][t];
                    s[i][0] += av * k0.x;
                    s[i][1] += av * k0.y;
                    s[i][2] += av * k0.z;
                    s[i][3] += av * k0.w;
                    s[i][4] += av * k1.x;
                    s[i][5] += av * k1.y;
                    s[i][6] += av * k1.z;
                    s[i][7] += av * k1.w;
                }
            }
        }

        // ---- Online softmax (row group = 16 lanes with same ty) ----
#pragma unroll
        for (int i = 0; i < 8; ++i) {
            float mx = s[i][0];
#pragma unroll
            for (int j = 1; j < 8; ++j) mx = fmaxf(mx, s[i][j]);
#pragma unroll
            for (int off = 8; off >= 1; off >>= 1)
                mx = fmaxf(mx, __shfl_xor_sync(0xffffffffu, mx, off, 16));
            float m_new = fmaxf(m_i[i], mx);
            float fac = __expf(m_i[i] - m_new);
            float p[8];
            float rs = 0.0f;
#pragma unroll
            for (int j = 0; j < 8; ++j) {
                p[j] = __expf(s[i][j] - m_new);
                rs += p[j];
            }
#pragma unroll
            for (int off = 8; off >= 1; off >>= 1)
                rs += __shfl_xor_sync(0xffffffffu, rs, off, 16);
            l_i[i] = l_i[i] * fac + rs;
            m_i[i] = m_new;
#pragma unroll
            for (int j = 0; j < 4; ++j) o[i][j] *= fac;
            *(float4*)&Ps[(r0 + i) * PST + c0k]      = make_float4(p[0], p[1], p[2], p[3]);
            *(float4*)&Ps[(r0 + i) * PST + 64 + c0k] = make_float4(p[4], p[5], p[6], p[7]);
        }
        __syncthreads();   // Ps visible to all threads

        // ---- O += P @ V  (8 q-rows x 4 dk per thread, over 128 keys) ----
#pragma unroll
        for (int k4 = 0; k4 < 32; ++k4) {
            float p[8][4];
#pragma unroll
            for (int i = 0; i < 8; ++i) {
                float4 pv = *(const float4*)&Ps[(r0 + i) * PST + k4 * 4];
                p[i][0] = pv.x; p[i][1] = pv.y; p[i][2] = pv.z; p[i][3] = pv.w;
            }
#pragma unroll
            for (int t = 0; t < 4; ++t) {
                float4 vv = *(const float4*)&Vs[(k4 * 4 + t) * VST + c0d];
#pragma unroll
                for (int i = 0; i < 8; ++i) {
                    float pt = p[i][t];
                    o[i][0] += pt * vv.x;
                    o[i][1] += pt * vv.y;
                    o[i][2] += pt * vv.z;
                    o[i][3] += pt * vv.w;
                }
            }
        }
    }

    // Write ctx[(b, s, h*64+d)]
#pragma unroll
    for (int i = 0; i < 8; ++i) {
        float inv = 1.0f / l_i[i];
        int srow = qt * BQ + r0 + i;
        float* dst = &ctx[((size_t)(b * SEQ + srow)) * DMODEL + h * 64 + c0d];
        *(float4*)dst = make_float4(o[i][0] * inv, o[i][1] * inv,
                                    o[i][2] * inv, o[i][3] * inv);
    }
}

// ---------------------------------------------------------------------------
// Launch
// ---------------------------------------------------------------------------
extern "C" void kernel_launch(void* const* d_in, const int* in_sizes, int n_in,
                              void* d_out, int out_size)
{
    const float* q  = (const float*)d_in[0];
    const float* k  = (const float*)d_in[1];
    const float* v  = (const float*)d_in[2];
    const float* Wq = (const float*)d_in[3];
    const float* bq = (const float*)d_in[4];
    const float* Wk = (const float*)d_in[5];
    const float* bk = (const float*)d_in[6];
    const float* Wv = (const float*)d_in[7];
    const float* bv = (const float*)d_in[8];
    const float* Wo = (const float*)d_in[9];
    const float* bo = (const float*)d_in[10];
    float* out = (float*)d_out;

    float *pQh, *pKh, *pVh, *pCtx;
    cudaGetSymbolAddress((void**)&pQh, g_Qh);
    cudaGetSymbolAddress((void**)&pKh, g_Kh);
    cudaGetSymbolAddress((void**)&pVh, g_Vh);
    cudaGetSymbolAddress((void**)&pCtx, g_ctx);

    cudaFuncSetAttribute(attn_kernel, cudaFuncAttributeMaxDynamicSharedMemorySize,
                         ATTN_SMEM);

    dim3 ggrid(DMODEL / 128, MROWS / 128);   // (8, 32)
    const float qscale = 0.125f;             // 1/sqrt(64)

    gemm_bias_kernel<1><<<ggrid, 256>>>(q, Wq, bq, pQh, qscale);
    gemm_bias_kernel<1><<<ggrid, 256>>>(k, Wk, bk, pKh, 1.0f);
    gemm_bias_kernel<1><<<ggrid, 256>>>(v, Wv, bv, pVh, 1.0f);

    dim3 agrid(SEQ / BQ, NHEADS, BATCH);     // (16, 16, 2)
    attn_kernel<<<agrid, 256, ATTN_SMEM>>>(pQh, pKh, pVh, pCtx);

    gemm_bias_kernel<0><<<ggrid, 256>>>(pCtx, Wo, bo, out, 1.0f);
}

// round 12
// speedup vs baseline: 2.0649x; 2.0649x over previous
#include <cuda_runtime.h>
#include <cuda_bf16.h>
#include <math.h>
#include <stdint.h>

// Problem constants
#define DMODEL 1024
#define NHEADS 16
#define DK     64
#define BATCH  2
#define SEQ    2048
#define MROWS  (BATCH*SEQ)   // 4096

// ---------------------------------------------------------------------------
// Scratch (device globals; allocation is forbidden)
// ---------------------------------------------------------------------------
__device__ float g_Qh[BATCH*NHEADS*SEQ*DK];
__device__ float g_Kh[BATCH*NHEADS*SEQ*DK];
__device__ float g_Vh[BATCH*NHEADS*SEQ*DK];
__device__ float g_ctx[BATCH*SEQ*DMODEL];
__device__ __nv_bfloat16 g_Ahi[MROWS*DMODEL];   // split A [M,K] (reused per GEMM)
__device__ __nv_bfloat16 g_Alo[MROWS*DMODEL];
__device__ __nv_bfloat16 g_Whi[DMODEL*DMODEL];  // split W^T [N,K] (reused)
__device__ __nv_bfloat16 g_Wlo[DMODEL*DMODEL];

// ---------------------------------------------------------------------------
// Split conversion: fp32 -> bf16 hi + bf16 lo (elementwise), vectorized x4
// ---------------------------------------------------------------------------
__global__ __launch_bounds__(256)
void split_kernel(const float* __restrict__ x,
                  __nv_bfloat16* __restrict__ hi,
                  __nv_bfloat16* __restrict__ lo, int n4)
{
    int i = blockIdx.x * 256 + threadIdx.x;
    if (i >= n4) return;
    float4 v = ((const float4*)x)[i];
    float f[4] = {v.x, v.y, v.z, v.w};
    uint32_t ph[2], pl[2];
#pragma unroll
    for (int j = 0; j < 2; ++j) {
        __nv_bfloat16 h0 = __float2bfloat16(f[2*j]);
        __nv_bfloat16 h1 = __float2bfloat16(f[2*j+1]);
        __nv_bfloat16 l0 = __float2bfloat16(f[2*j]   - __bfloat162float(h0));
        __nv_bfloat16 l1 = __float2bfloat16(f[2*j+1] - __bfloat162float(h1));
        ph[j] = (uint32_t)__bfloat16_as_ushort(h0) | ((uint32_t)__bfloat16_as_ushort(h1) << 16);
        pl[j] = (uint32_t)__bfloat16_as_ushort(l0) | ((uint32_t)__bfloat16_as_ushort(l1) << 16);
    }
    ((uint2*)hi)[i] = make_uint2(ph[0], ph[1]);
    ((uint2*)lo)[i] = make_uint2(pl[0], pl[1]);
}

// Transposed split: W[K,N] fp32 -> hi/lo bf16 [N,K]
__global__ __launch_bounds__(256)
void splitT_kernel(const float* __restrict__ W,
                   __nv_bfloat16* __restrict__ hi,
                   __nv_bfloat16* __restrict__ lo)
{
    __shared__ float t[32][33];
    const int n0 = blockIdx.x * 32, k0 = blockIdx.y * 32;
    const int tx = threadIdx.x & 31, ty = threadIdx.x >> 5;  // 32 x 8
#pragma unroll
    for (int j = 0; j < 32; j += 8)
        t[ty + j][tx] = W[(size_t)(k0 + ty + j) * DMODEL + n0 + tx];
    __syncthreads();
#pragma unroll
    for (int j = 0; j < 32; j += 8) {
        float f = t[tx][ty + j];
        __nv_bfloat16 h = __float2bfloat16(f);
        __nv_bfloat16 l = __float2bfloat16(f - __bfloat162float(h));
        size_t o = (size_t)(n0 + ty + j) * DMODEL + k0 + tx;
        hi[o] = h;
        lo[o] = l;
    }
}

// ---------------------------------------------------------------------------
// mma.sync bf16x3 GEMM: C[m,n] = (sum_k A[m,k]*W[k,n] + bias[n]) * scale
//   A split: Ahi/Alo [M,K] bf16 ; B split: Bhi/Blo [N,K] bf16 (W transposed)
//   C = Ah*Bh + Ah*Bl + Al*Bh  in fp32 accumulators.
// CTA: 128x128 tile, BK=32, 256 threads = 8 warps (2 m x 4 n), warp 64x32.
// Smem rows padded to 80 B -> conflict-free LDS.32 fragment loads.
// Double-buffered via cp.async.
// ---------------------------------------------------------------------------
#define KPADB 80                      // bytes per 32-k row (32*2 + 16 pad)
#define GBUF  (128 * KPADB)           // 10240 B per operand buffer
#define GSTG  (4 * GBUF)              // 40960 B per stage
#define G_AHI 0
#define G_ALO (1 * GBUF)
#define G_BHI (2 * GBUF)
#define G_BLO (3 * GBUF)
#define GSMEM (2 * GSTG)              // 81920 B

__device__ __forceinline__ void mma_bf16(float* d, const uint32_t* a, const uint32_t* b) {
    asm volatile(
        "mma.sync.aligned.m16n8k16.row.col.f32.bf16.bf16.f32 "
        "{%0,%1,%2,%3}, {%4,%5,%6,%7}, {%8,%9}, {%0,%1,%2,%3};"
        : "+f"(d[0]), "+f"(d[1]), "+f"(d[2]), "+f"(d[3])
        : "r"(a[0]), "r"(a[1]), "r"(a[2]), "r"(a[3]), "r"(b[0]), "r"(b[1]));
}

__device__ __forceinline__ void cp_async16(void* dst_smem, const void* src) {
    uint32_t d;
    asm("{ .reg .u64 t; cvta.to.shared.u64 t, %1; cvt.u32.u64 %0, t; }"
        : "=r"(d) : "l"(dst_smem));
    asm volatile("cp.async.cg.shared.global [%0], [%1], 16;" :: "r"(d), "l"(src));
}

template <int HEAD_MODE>
__global__ __launch_bounds__(256)
void gemm_tc_kernel(const __nv_bfloat16* __restrict__ Ahi,
                    const __nv_bfloat16* __restrict__ Alo,
                    const __nv_bfloat16* __restrict__ Bhi,
                    const __nv_bfloat16* __restrict__ Blo,
                    const float* __restrict__ bias,
                    float* __restrict__ C, float scale)
{
    extern __shared__ char sm[];
    const int tid  = threadIdx.x;
    const int wid  = tid >> 5;
    const int lane = tid & 31;
    const int g  = lane >> 2;          // 0..7
    const int tq = lane & 3;           // 0..3
    const int warp_m = wid >> 2;       // 0..1 (64 rows each)
    const int warp_n = wid & 3;        // 0..3 (32 cols each)
    const int nbase = blockIdx.x * 128;
    const int mbase = blockIdx.y * 128;
    constexpr int K = DMODEL;
    constexpr int NCHUNK = K / 32;     // 32

    // cp.async mapping: per buffer 512 x 16B; 2 per thread
    const int ld_row = tid >> 2;       // 0..63 (+64 on second it)
    const int ld_g2  = tid & 3;        // 16B group: 8 bf16

    auto issue_chunk = [&](int chunk, int stage) {
        char* stg = sm + stage * GSTG;
        const int k0 = chunk * 32;
#pragma unroll
        for (int it = 0; it < 2; ++it) {
            int row = ld_row + it * 64;
            size_t ga = (size_t)(mbase + row) * K + k0 + ld_g2 * 8;
            size_t gb = (size_t)(nbase + row) * K + k0 + ld_g2 * 8;
            int so = row * KPADB + ld_g2 * 16;
            cp_async16(stg + G_AHI + so, Ahi + ga);
            cp_async16(stg + G_ALO + so, Alo + ga);
            cp_async16(stg + G_BHI + so, Bhi + gb);
            cp_async16(stg + G_BLO + so, Blo + gb);
        }
        asm volatile("cp.async.commit_group;" ::: "memory");
    };

    float acc[4][4][4];
#pragma unroll
    for (int i = 0; i < 4; ++i)
#pragma unroll
        for (int j = 0; j < 4; ++j)
#pragma unroll
            for (int r = 0; r < 4; ++r) acc[i][j][r] = 0.0f;

    issue_chunk(0, 0);
    issue_chunk(1, 1);

    // Per-thread fragment byte offsets (within a stage)
    const int a_row0 = warp_m * 64 + g;         // + mt*16, +8 for second row
    const int b_row0 = warp_n * 32 + g;         // + nt*8

    for (int ch = 0; ch < NCHUNK; ++ch) {
        const int stage = ch & 1;
        char* stg = sm + stage * GSTG;
        asm volatile("cp.async.wait_group 1;" ::: "memory");
        __syncthreads();

#pragma unroll
        for (int kb = 0; kb < 2; ++kb) {        // two k16 steps
            const int kByte = kb * 32 + tq * 4; // (kb*16 + 2tq) bf16 -> bytes

            uint32_t a_hi[4][4], a_lo[4][4];
#pragma unroll
            for (int mt = 0; mt < 4; ++mt) {
                int base = (a_row0 + mt * 16) * KPADB + kByte;
                a_hi[mt][0] = *(const uint32_t*)(stg + G_AHI + base);
                a_hi[mt][1] = *(const uint32_t*)(stg + G_AHI + base + 8 * KPADB);
                a_hi[mt][2] = *(const uint32_t*)(stg + G_AHI + base + 16);
                a_hi[mt][3] = *(const uint32_t*)(stg + G_AHI + base + 8 * KPADB + 16);
                a_lo[mt][0] = *(const uint32_t*)(stg + G_ALO + base);
                a_lo[mt][1] = *(const uint32_t*)(stg + G_ALO + base + 8 * KPADB);
                a_lo[mt][2] = *(const uint32_t*)(stg + G_ALO + base + 16);
                a_lo[mt][3] = *(const uint32_t*)(stg + G_ALO + base + 8 * KPADB + 16);
            }
            uint32_t b_hi[4][2], b_lo[4][2];
#pragma unroll
            for (int nt = 0; nt < 4; ++nt) {
                int base = (b_row0 + nt * 8) * KPADB + kByte;
                b_hi[nt][0] = *(const uint32_t*)(stg + G_BHI + base);
                b_hi[nt][1] = *(const uint32_t*)(stg + G_BHI + base + 16);
                b_lo[nt][0] = *(const uint32_t*)(stg + G_BLO + base);
                b_lo[nt][1] = *(const uint32_t*)(stg + G_BLO + base + 16);
            }
#pragma unroll
            for (int mt = 0; mt < 4; ++mt)
#pragma unroll
                for (int nt = 0; nt < 4; ++nt) {
                    mma_bf16(acc[mt][nt], a_hi[mt], b_hi[nt]);
                    mma_bf16(acc[mt][nt], a_hi[mt], b_lo[nt]);
                    mma_bf16(acc[mt][nt], a_lo[mt], b_hi[nt]);
                }
        }

        __syncthreads();
        if (ch + 2 < NCHUNK) issue_chunk(ch + 2, stage);
    }

    // Epilogue: acc[mt][nt] = C[rows a_row0+mt*16 {+0,+8}][cols nb+2tq {,+1}]
#pragma unroll
    for (int mt = 0; mt < 4; ++mt) {
#pragma unroll
        for (int half = 0; half < 2; ++half) {
            int m = mbase + warp_m * 64 + mt * 16 + g + half * 8;
#pragma unroll
            for (int nt = 0; nt < 4; ++nt) {
                int n = nbase + warp_n * 32 + nt * 8 + tq * 2;
                float2 o;
                o.x = (acc[mt][nt][half * 2 + 0] + bias[n + 0]) * scale;
                o.y = (acc[mt][nt][half * 2 + 1] + bias[n + 1]) * scale;
                if (HEAD_MODE) {
                    int b = m >> 11, s = m & 2047;
                    int h = n >> 6,  d = n & 63;
                    *(float2*)&C[(((size_t)(b * NHEADS + h)) * SEQ + s) * DK + d] = o;
                } else {
                    *(float2*)&C[(size_t)m * DMODEL + n] = o;
                }
            }
        }
    }
}

// ---------------------------------------------------------------------------
// Flash attention (R2 known-good: 64x64 tiles, 4x4/thread, fp32)
// ---------------------------------------------------------------------------
#define AST 68
#define ATTN_SMEM (4 * 64 * AST * 4)

__global__ __launch_bounds__(256)
void attn_kernel(const float* __restrict__ Qh,
                 const float* __restrict__ Kh,
                 const float* __restrict__ Vh,
                 float* __restrict__ ctx)
{
    extern __shared__ float smf[];
    float* Qs = smf;
    float* Kt = smf + 64 * AST;
    float* Vs = smf + 2 * 64 * AST;
    float* Ps = smf + 3 * 64 * AST;

    const int tid = threadIdx.x;
    const int tx  = tid & 15;
    const int ty  = tid >> 4;
    const int qt = blockIdx.x;
    const int h  = blockIdx.y;
    const int b  = blockIdx.z;

    const float* Qbase = Qh + (((size_t)(b * NHEADS + h)) * SEQ + qt * 64) * DK;
    const float* Kbase = Kh + ((size_t)(b * NHEADS + h)) * SEQ * DK;
    const float* Vbase = Vh + ((size_t)(b * NHEADS + h)) * SEQ * DK;

#pragma unroll
    for (int it = 0; it < 4; ++it) {
        int idx = tid + it * 256;
        int row = idx >> 4;
        int d4  = idx & 15;
        float4 v = *(const float4*)&Qbase[row * DK + d4 * 4];
        *(float4*)&Qs[row * AST + d4 * 4] = v;
    }

    float m_i[4], l_i[4], o[4][4];
#pragma unroll
    for (int i = 0; i < 4; ++i) {
        m_i[i] = -INFINITY;
        l_i[i] = 0.0f;
#pragma unroll
        for (int j = 0; j < 4; ++j) o[i][j] = 0.0f;
    }

    const int r0 = ty * 4;
    const int c0 = tx * 4;

    for (int kb = 0; kb < SEQ / 64; ++kb) {
        __syncthreads();
#pragma unroll
        for (int it = 0; it < 4; ++it) {
            int idx = tid + it * 256;
            int r  = idx >> 4;
            int d4 = idx & 15;
            float4 kv = *(const float4*)&Kbase[(size_t)(kb * 64 + r) * DK + d4 * 4];
            Kt[(d4 * 4 + 0) * AST + r] = kv.x;
            Kt[(d4 * 4 + 1) * AST + r] = kv.y;
            Kt[(d4 * 4 + 2) * AST + r] = kv.z;
            Kt[(d4 * 4 + 3) * AST + r] = kv.w;
            float4 vv = *(const float4*)&Vbase[(size_t)(kb * 64 + r) * DK + d4 * 4];
            *(float4*)&Vs[r * AST + d4 * 4] = vv;
        }
        __syncthreads();

        float s[4][4];
#pragma unroll
        for (int i = 0; i < 4; ++i)
#pragma unroll
            for (int j = 0; j < 4; ++j) s[i][j] = 0.0f;

#pragma unroll
        for (int d4 = 0; d4 < 16; ++d4) {
            float a[4][4];
#pragma unroll
            for (int i = 0; i < 4; ++i) {
                float4 q = *(const float4*)&Qs[(r0 + i) * AST + d4 * 4];
                a[i][0] = q.x; a[i][1] = q.y; a[i][2] = q.z; a[i][3] = q.w;
            }
#pragma unroll
            for (int t = 0; t < 4; ++t) {
                float4 kv = *(const float4*)&Kt[(d4 * 4 + t) * AST + c0];
#pragma unroll
                for (int i = 0; i < 4; ++i) {
                    s[i][0] += a[i][t] * kv.x;
                    s[i][1] += a[i][t] * kv.y;
                    s[i][2] += a[i][t] * kv.z;
                    s[i][3] += a[i][t] * kv.w;
                }
            }
        }

#pragma unroll
        for (int i = 0; i < 4; ++i) {
            float mx = fmaxf(fmaxf(s[i][0], s[i][1]), fmaxf(s[i][2], s[i][3]));
#pragma unroll
            for (int off = 8; off >= 1; off >>= 1)
                mx = fmaxf(mx, __shfl_xor_sync(0xffffffffu, mx, off, 16));
            float m_new = fmaxf(m_i[i], mx);
            float fac = __expf(m_i[i] - m_new);
            float p0 = __expf(s[i][0] - m_new);
            float p1 = __expf(s[i][1] - m_new);
            float p2 = __expf(s[i][2] - m_new);
            float p3 = __expf(s[i][3] - m_new);
            float rs = (p0 + p1) + (p2 + p3);
#pragma unroll
            for (int off = 8; off >= 1; off >>= 1)
                rs += __shfl_xor_sync(0xffffffffu, rs, off, 16);
            l_i[i] = l_i[i] * fac + rs;
            m_i[i] = m_new;
#pragma unroll
            for (int j = 0; j < 4; ++j) o[i][j] *= fac;
            *(float4*)&Ps[(r0 + i) * AST + c0] = make_float4(p0, p1, p2, p3);
        }
        __syncthreads();

#pragma unroll
        for (int k4 = 0; k4 < 16; ++k4) {
            float p[4][4];
#pragma unroll
            for (int i = 0; i < 4; ++i) {
                float4 pv = *(const float4*)&Ps[(r0 + i) * AST + k4 * 4];
                p[i][0] = pv.x; p[i][1] = pv.y; p[i][2] = pv.z; p[i][3] = pv.w;
            }
#pragma unroll
            for (int t = 0; t < 4; ++t) {
                float4 vv = *(const float4*)&Vs[(k4 * 4 + t) * AST + c0];
#pragma unroll
                for (int i = 0; i < 4; ++i) {
                    o[i][0] += p[i][t] * vv.x;
                    o[i][1] += p[i][t] * vv.y;
                    o[i][2] += p[i][t] * vv.z;
                    o[i][3] += p[i][t] * vv.w;
                }
            }
        }
    }

#pragma unroll
    for (int i = 0; i < 4; ++i) {
        float inv = 1.0f / l_i[i];
        int srow = qt * 64 + r0 + i;
        float* dst = &ctx[((size_t)(b * SEQ + srow)) * DMODEL + h * 64 + c0];
        *(float4*)dst = make_float4(o[i][0] * inv, o[i][1] * inv,
                                    o[i][2] * inv, o[i][3] * inv);
    }
}

// ---------------------------------------------------------------------------
// Launch
// ---------------------------------------------------------------------------
extern "C" void kernel_launch(void* const* d_in, const int* in_sizes, int n_in,
                              void* d_out, int out_size)
{
    const float* q  = (const float*)d_in[0];
    const float* k  = (const float*)d_in[1];
    const float* v  = (const float*)d_in[2];
    const float* Wq = (const float*)d_in[3];
    const float* bq = (const float*)d_in[4];
    const float* Wk = (const float*)d_in[5];
    const float* bk = (const float*)d_in[6];
    const float* Wv = (const float*)d_in[7];
    const float* bv = (const float*)d_in[8];
    const float* Wo = (const float*)d_in[9];
    const float* bo = (const float*)d_in[10];
    float* out = (float*)d_out;

    float *pQh, *pKh, *pVh, *pCtx;
    __nv_bfloat16 *pAhi, *pAlo, *pWhi, *pWlo;
    cudaGetSymbolAddress((void**)&pQh,  g_Qh);
    cudaGetSymbolAddress((void**)&pKh,  g_Kh);
    cudaGetSymbolAddress((void**)&pVh,  g_Vh);
    cudaGetSymbolAddress((void**)&pCtx, g_ctx);
    cudaGetSymbolAddress((void**)&pAhi, g_Ahi);
    cudaGetSymbolAddress((void**)&pAlo, g_Alo);
    cudaGetSymbolAddress((void**)&pWhi, g_Whi);
    cudaGetSymbolAddress((void**)&pWlo, g_Wlo);

    cudaFuncSetAttribute(attn_kernel, cudaFuncAttributeMaxDynamicSharedMemorySize,
                         ATTN_SMEM);
    cudaFuncSetAttribute(gemm_tc_kernel<0>, cudaFuncAttributeMaxDynamicSharedMemorySize,
                         GSMEM);
    cudaFuncSetAttribute(gemm_tc_kernel<1>, cudaFuncAttributeMaxDynamicSharedMemorySize,
                         GSMEM);

    const int nA4 = MROWS * DMODEL / 4;
    dim3 sgrid((nA4 + 255) / 256);
    dim3 tgrid(DMODEL / 32, DMODEL / 32);
    dim3 ggrid(DMODEL / 128, MROWS / 128);           // (8, 32)
    const float qscale = 0.125f;                     // 1/sqrt(64)

    // Q projection
    splitT_kernel<<<tgrid, 256>>>(Wq, pWhi, pWlo);
    split_kernel<<<sgrid, 256>>>(q, pAhi, pAlo, nA4);
    gemm_tc_kernel<1><<<ggrid, 256, GSMEM>>>(pAhi, pAlo, pWhi, pWlo, bq, pQh, qscale);
    // K projection
    splitT_kernel<<<tgrid, 256>>>(Wk, pWhi, pWlo);
    split_kernel<<<sgrid, 256>>>(k, pAhi, pAlo, nA4);
    gemm_tc_kernel<1><<<ggrid, 256, GSMEM>>>(pAhi, pAlo, pWhi, pWlo, bk, pKh, 1.0f);
    // V projection
    splitT_kernel<<<tgrid, 256>>>(Wv, pWhi, pWlo);
    split_kernel<<<sgrid, 256>>>(v, pAhi, pAlo, nA4);
    gemm_tc_kernel<1><<<ggrid, 256, GSMEM>>>(pAhi, pAlo, pWhi, pWlo, bv, pVh, 1.0f);

    // Attention (fp32, known-good)
    dim3 agrid(SEQ / 64, NHEADS, BATCH);
    attn_kernel<<<agrid, 256, ATTN_SMEM>>>(pQh, pKh, pVh, pCtx);

    // Output projection
    splitT_kernel<<<tgrid, 256>>>(Wo, pWhi, pWlo);
    split_kernel<<<sgrid, 256>>>(pCtx, pAhi, pAlo, nA4);
    gemm_tc_kernel<0><<<ggrid, 256, GSMEM>>>(pAhi, pAlo, pWhi, pWlo, bo, out, 1.0f);
}

// round 14
// speedup vs baseline: 3.6842x; 1.7842x over previous
#include <cuda_runtime.h>
#include <cuda_bf16.h>
#include <math.h>
#include <stdint.h>

// Problem constants
#define DMODEL 1024
#define NHEADS 16
#define DK     64
#define BATCH  2
#define SEQ    2048
#define MROWS  (BATCH*SEQ)   // 4096

// ---------------------------------------------------------------------------
// Scratch (device globals; allocation is forbidden)
// ---------------------------------------------------------------------------
__device__ __nv_bfloat16 g_Ahi[MROWS*DMODEL];   // input/ctx split A [M,K]
__device__ __nv_bfloat16 g_Alo[MROWS*DMODEL];
__device__ __nv_bfloat16 g_Whi[DMODEL*DMODEL];  // weight split W^T [N,K]
__device__ __nv_bfloat16 g_Wlo[DMODEL*DMODEL];
__device__ __nv_bfloat16 g_Qhi[BATCH*NHEADS*SEQ*DK];  // heads layout, Q pre-scaled
__device__ __nv_bfloat16 g_Qlo[BATCH*NHEADS*SEQ*DK];
__device__ __nv_bfloat16 g_Khi[BATCH*NHEADS*SEQ*DK];
__device__ __nv_bfloat16 g_Klo[BATCH*NHEADS*SEQ*DK];
__device__ __nv_bfloat16 g_Vhi[BATCH*NHEADS*SEQ*DK];
__device__ __nv_bfloat16 g_Vlo[BATCH*NHEADS*SEQ*DK];

// ---------------------------------------------------------------------------
// Helpers
// ---------------------------------------------------------------------------
__device__ __forceinline__ uint32_t smem_u32(const void* p) {
    uint32_t a;
    asm("{ .reg .u64 t; cvta.to.shared.u64 t, %1; cvt.u32.u64 %0, t; }"
        : "=r"(a) : "l"(p));
    return a;
}
__device__ __forceinline__ void cp16s(uint32_t dst, const void* src) {
    asm volatile("cp.async.cg.shared.global [%0], [%1], 16;" :: "r"(dst), "l"(src));
}
__device__ __forceinline__ void cp16(void* dst_smem, const void* src) {
    cp16s(smem_u32(dst_smem), src);
}
#define CP_COMMIT() asm volatile("cp.async.commit_group;" ::: "memory")
#define CP_WAIT(n)  asm volatile("cp.async.wait_group %0;" :: "n"(n) : "memory")

__device__ __forceinline__ void mma_bf16(float* d, const uint32_t* a, const uint32_t* b) {
    asm volatile(
        "mma.sync.aligned.m16n8k16.row.col.f32.bf16.bf16.f32 "
        "{%0,%1,%2,%3}, {%4,%5,%6,%7}, {%8,%9}, {%0,%1,%2,%3};"
        : "+f"(d[0]), "+f"(d[1]), "+f"(d[2]), "+f"(d[3])
        : "r"(a[0]), "r"(a[1]), "r"(a[2]), "r"(a[3]), "r"(b[0]), "r"(b[1]));
}
#define LDMX4(r, a) \
    asm volatile("ldmatrix.sync.aligned.m8n8.x4.shared.b16 {%0,%1,%2,%3}, [%4];" \
        : "=r"((r)[0]), "=r"((r)[1]), "=r"((r)[2]), "=r"((r)[3]) : "r"(a))
#define LDMX4T(r, a) \
    asm volatile("ldmatrix.sync.aligned.m8n8.x4.trans.shared.b16 {%0,%1,%2,%3}, [%4];" \
        : "=r"((r)[0]), "=r"((r)[1]), "=r"((r)[2]), "=r"((r)[3]) : "r"(a))

__device__ __forceinline__ uint32_t pack_bf2(__nv_bfloat16 lo, __nv_bfloat16 hi) {
    return (uint32_t)__bfloat16_as_ushort(lo) | ((uint32_t)__bfloat16_as_ushort(hi) << 16);
}
// split (x,y) -> packed hi pair + packed lo pair
__device__ __forceinline__ void split2(float x, float y, uint32_t& hi, uint32_t& lo) {
    __nv_bfloat16 hx = __float2bfloat16(x);
    __nv_bfloat16 hy = __float2bfloat16(y);
    __nv_bfloat16 lx = __float2bfloat16(x - __bfloat162float(hx));
    __nv_bfloat16 ly = __float2bfloat16(y - __bfloat162float(hy));
    hi = pack_bf2(hx, hy);
    lo = pack_bf2(lx, ly);
}

// ---------------------------------------------------------------------------
// Split conversion kernels (inputs + weights)
// ---------------------------------------------------------------------------
__global__ __launch_bounds__(256)
void split_kernel(const float* __restrict__ x,
                  __nv_bfloat16* __restrict__ hi,
                  __nv_bfloat16* __restrict__ lo, int n4)
{
    int i = blockIdx.x * 256 + threadIdx.x;
    if (i >= n4) return;
    float4 v = ((const float4*)x)[i];
    uint32_t h0, l0, h1, l1;
    split2(v.x, v.y, h0, l0);
    split2(v.z, v.w, h1, l1);
    ((uint2*)hi)[i] = make_uint2(h0, h1);
    ((uint2*)lo)[i] = make_uint2(l0, l1);
}

__global__ __launch_bounds__(256)
void splitT_kernel(const float* __restrict__ W,
                   __nv_bfloat16* __restrict__ hi,
                   __nv_bfloat16* __restrict__ lo)
{
    __shared__ float t[32][33];
    const int n0 = blockIdx.x * 32, k0 = blockIdx.y * 32;
    const int tx = threadIdx.x & 31, ty = threadIdx.x >> 5;
#pragma unroll
    for (int j = 0; j < 32; j += 8)
        t[ty + j][tx] = W[(size_t)(k0 + ty + j) * DMODEL + n0 + tx];
    __syncthreads();
#pragma unroll
    for (int j = 0; j < 32; j += 8) {
        float f = t[tx][ty + j];
        __nv_bfloat16 h = __float2bfloat16(f);
        __nv_bfloat16 l = __float2bfloat16(f - __bfloat162float(h));
        size_t o = (size_t)(n0 + ty + j) * DMODEL + k0 + tx;
        hi[o] = h;
        lo[o] = l;
    }
}

// ---------------------------------------------------------------------------
// mma.sync bf16x3 GEMM (from R12, epilogue now emits bf16 hi/lo in head mode)
// ---------------------------------------------------------------------------
#define KPADB 80
#define GBUF  (128 * KPADB)
#define GSTG  (4 * GBUF)
#define G_AHI 0
#define G_ALO (1 * GBUF)
#define G_BHI (2 * GBUF)
#define G_BLO (3 * GBUF)
#define GSMEM (2 * GSTG)

template <int HEAD_MODE>
__global__ __launch_bounds__(256)
void gemm_tc_kernel(const __nv_bfloat16* __restrict__ Ahi,
                    const __nv_bfloat16* __restrict__ Alo,
                    const __nv_bfloat16* __restrict__ Bhi,
                    const __nv_bfloat16* __restrict__ Blo,
                    const float* __restrict__ bias,
                    float* __restrict__ C,                 // HEAD_MODE=0
                    __nv_bfloat16* __restrict__ Ohi,       // HEAD_MODE=1
                    __nv_bfloat16* __restrict__ Olo,
                    float scale)
{
    extern __shared__ char sm[];
    const int tid  = threadIdx.x;
    const int wid  = tid >> 5;
    const int lane = tid & 31;
    const int g  = lane >> 2;
    const int tq = lane & 3;
    const int warp_m = wid >> 2;
    const int warp_n = wid & 3;
    const int nbase = blockIdx.x * 128;
    const int mbase = blockIdx.y * 128;
    constexpr int K = DMODEL;
    constexpr int NCHUNK = K / 32;

    const int ld_row = tid >> 2;
    const int ld_g2  = tid & 3;

    auto issue_chunk = [&](int chunk, int stage) {
        char* stg = sm + stage * GSTG;
        const int k0 = chunk * 32;
#pragma unroll
        for (int it = 0; it < 2; ++it) {
            int row = ld_row + it * 64;
            size_t ga = (size_t)(mbase + row) * K + k0 + ld_g2 * 8;
            size_t gb = (size_t)(nbase + row) * K + k0 + ld_g2 * 8;
            int so = row * KPADB + ld_g2 * 16;
            cp16(stg + G_AHI + so, Ahi + ga);
            cp16(stg + G_ALO + so, Alo + ga);
            cp16(stg + G_BHI + so, Bhi + gb);
            cp16(stg + G_BLO + so, Blo + gb);
        }
        CP_COMMIT();
    };

    float acc[4][4][4];
#pragma unroll
    for (int i = 0; i < 4; ++i)
#pragma unroll
        for (int j = 0; j < 4; ++j)
#pragma unroll
            for (int r = 0; r < 4; ++r) acc[i][j][r] = 0.0f;

    issue_chunk(0, 0);
    issue_chunk(1, 1);

    const int a_row0 = warp_m * 64 + g;
    const int b_row0 = warp_n * 32 + g;

    for (int ch = 0; ch < NCHUNK; ++ch) {
        const int stage = ch & 1;
        char* stg = sm + stage * GSTG;
        CP_WAIT(1);
        __syncthreads();

#pragma unroll
        for (int kb = 0; kb < 2; ++kb) {
            const int kByte = kb * 32 + tq * 4;
            uint32_t a_hi[4][4], a_lo[4][4];
#pragma unroll
            for (int mt = 0; mt < 4; ++mt) {
                int base = (a_row0 + mt * 16) * KPADB + kByte;
                a_hi[mt][0] = *(const uint32_t*)(stg + G_AHI + base);
                a_hi[mt][1] = *(const uint32_t*)(stg + G_AHI + base + 8 * KPADB);
                a_hi[mt][2] = *(const uint32_t*)(stg + G_AHI + base + 16);
                a_hi[mt][3] = *(const uint32_t*)(stg + G_AHI + base + 8 * KPADB + 16);
                a_lo[mt][0] = *(const uint32_t*)(stg + G_ALO + base);
                a_lo[mt][1] = *(const uint32_t*)(stg + G_ALO + base + 8 * KPADB);
                a_lo[mt][2] = *(const uint32_t*)(stg + G_ALO + base + 16);
                a_lo[mt][3] = *(const uint32_t*)(stg + G_ALO + base + 8 * KPADB + 16);
            }
            uint32_t b_hi[4][2], b_lo[4][2];
#pragma unroll
            for (int nt = 0; nt < 4; ++nt) {
                int base = (b_row0 + nt * 8) * KPADB + kByte;
                b_hi[nt][0] = *(const uint32_t*)(stg + G_BHI + base);
                b_hi[nt][1] = *(const uint32_t*)(stg + G_BHI + base + 16);
                b_lo[nt][0] = *(const uint32_t*)(stg + G_BLO + base);
                b_lo[nt][1] = *(const uint32_t*)(stg + G_BLO + base + 16);
            }
#pragma unroll
            for (int mt = 0; mt < 4; ++mt)
#pragma unroll
                for (int nt = 0; nt < 4; ++nt) {
                    mma_bf16(acc[mt][nt], a_hi[mt], b_hi[nt]);
                    mma_bf16(acc[mt][nt], a_hi[mt], b_lo[nt]);
                    mma_bf16(acc[mt][nt], a_lo[mt], b_hi[nt]);
                }
        }

        __syncthreads();
        if (ch + 2 < NCHUNK) issue_chunk(ch + 2, stage);
    }

#pragma unroll
    for (int mt = 0; mt < 4; ++mt) {
#pragma unroll
        for (int half = 0; half < 2; ++half) {
            int m = mbase + warp_m * 64 + mt * 16 + g + half * 8;
#pragma unroll
            for (int nt = 0; nt < 4; ++nt) {
                int n = nbase + warp_n * 32 + nt * 8 + tq * 2;
                float ox = (acc[mt][nt][half * 2 + 0] + bias[n + 0]) * scale;
                float oy = (acc[mt][nt][half * 2 + 1] + bias[n + 1]) * scale;
                if (HEAD_MODE) {
                    int b = m >> 11, s = m & 2047;
                    int hh = n >> 6, d = n & 63;
                    size_t idx = (((size_t)(b * NHEADS + hh)) * SEQ + s) * DK + d;
                    uint32_t hi, lo;
                    split2(ox, oy, hi, lo);
                    *(uint32_t*)&Ohi[idx] = hi;
                    *(uint32_t*)&Olo[idx] = lo;
                } else {
                    *(float2*)&C[(size_t)m * DMODEL + n] = make_float2(ox, oy);
                }
            }
        }
    }
}

// ---------------------------------------------------------------------------
// Flash attention on mma.sync (bf16x3).  CTA = 128 q-rows x 64-key blocks.
// 8 warps, each owns 16 q-rows.  Q/K/V given as bf16 hi/lo head-layout arrays.
// Output: ctx split hi/lo written straight into the final GEMM's A buffers.
// Smem rows padded to 72 bf16 (144 B) -> conflict-free ldmatrix.
// ---------------------------------------------------------------------------
#define ASTRIDE 72
#define AQ_HI   0
#define AQ_LO   18432                  // 128*72*2
#define ASTG0   36864
#define ASTGSZ  36864                  // 4 * 64*72*2
#define AK_HI   0
#define AK_LO   9216
#define AV_HI   18432
#define AV_LO   27648
#define AMMA_SMEM (ASTG0 + 2 * ASTGSZ) // 110592

__global__ __launch_bounds__(256)
void attn_mma_kernel(const __nv_bfloat16* __restrict__ Qhi,
                     const __nv_bfloat16* __restrict__ Qlo,
                     const __nv_bfloat16* __restrict__ Khi,
                     const __nv_bfloat16* __restrict__ Klo,
                     const __nv_bfloat16* __restrict__ Vhi,
                     const __nv_bfloat16* __restrict__ Vlo,
                     __nv_bfloat16* __restrict__ Chi,
                     __nv_bfloat16* __restrict__ Clo)
{
    extern __shared__ char smc[];
    const uint32_t sb = smem_u32(smc);

    const int tid = threadIdx.x;
    const int wid = tid >> 5;
    const int lane = tid & 31;
    const int g  = lane >> 2;
    const int qd = lane & 3;
    const int qt = blockIdx.x;
    const int h  = blockIdx.y;
    const int b  = blockIdx.z;

    const size_t bh = (size_t)(b * NHEADS + h) * SEQ;
    const __nv_bfloat16* Qh_g = Qhi + (bh + (size_t)qt * 128) * DK;
    const __nv_bfloat16* Ql_g = Qlo + (bh + (size_t)qt * 128) * DK;
    const __nv_bfloat16* Kh_g = Khi + bh * DK;
    const __nv_bfloat16* Kl_g = Klo + bh * DK;
    const __nv_bfloat16* Vh_g = Vhi + bh * DK;
    const __nv_bfloat16* Vl_g = Vlo + bh * DK;

    // ---- Q stage (once): 128 rows x 8 x16B per array ----
#pragma unroll
    for (int it = 0; it < 4; ++it) {
        int idx = tid + it * 256;          // 0..1023
        int row = idx >> 3;
        int gg  = idx & 7;
        uint32_t off = (uint32_t)(row * ASTRIDE + gg * 8) * 2;
        cp16s(sb + AQ_HI + off, Qh_g + row * DK + gg * 8);
        cp16s(sb + AQ_LO + off, Ql_g + row * DK + gg * 8);
    }
    CP_COMMIT();

    auto load_kv = [&](int blk, int s) {
        uint32_t stg = sb + ASTG0 + s * ASTGSZ;
        const __nv_bfloat16* kh = Kh_g + (size_t)blk * 64 * DK;
        const __nv_bfloat16* kl = Kl_g + (size_t)blk * 64 * DK;
        const __nv_bfloat16* vh = Vh_g + (size_t)blk * 64 * DK;
        const __nv_bfloat16* vl = Vl_g + (size_t)blk * 64 * DK;
#pragma unroll
        for (int it = 0; it < 2; ++it) {
            int idx = tid + it * 256;      // 0..511
            int row = idx >> 3;
            int gg  = idx & 7;
            uint32_t off = (uint32_t)(row * ASTRIDE + gg * 8) * 2;
            const int go = row * DK + gg * 8;
            cp16s(stg + AK_HI + off, kh + go);
            cp16s(stg + AK_LO + off, kl + go);
            cp16s(stg + AV_HI + off, vh + go);
            cp16s(stg + AV_LO + off, vl + go);
        }
        CP_COMMIT();
    };

    load_kv(0, 0);
    load_kv(1, 1);

    // ldmatrix lane->element offsets
    const int q_r = lane & 15;
    const int q_c = (lane & 16) ? 8 : 0;
    const int k_r = (lane & 7) + ((lane & 16) ? 8 : 0);
    const int k_c = (lane & 8) ? 8 : 0;
    const int v_r = (lane & 7) + ((lane & 8) ? 8 : 0);
    const int v_c = (lane & 16) ? 8 : 0;

    CP_WAIT(2);
    __syncthreads();

    // Q fragments (persist in registers)
    uint32_t qh[4][4], ql[4][4];
    const int qrow0 = wid * 16;
#pragma unroll
    for (int ks = 0; ks < 4; ++ks) {
        uint32_t a = sb + AQ_HI + (uint32_t)((qrow0 + q_r) * ASTRIDE + ks * 16 + q_c) * 2;
        LDMX4(qh[ks], a);
        a = sb + AQ_LO + (uint32_t)((qrow0 + q_r) * ASTRIDE + ks * 16 + q_c) * 2;
        LDMX4(ql[ks], a);
    }

    float m_i[2] = {-INFINITY, -INFINITY};
    float l_i[2] = {0.0f, 0.0f};
    float o[8][4];
#pragma unroll
    for (int i = 0; i < 8; ++i)
#pragma unroll
        for (int j = 0; j < 4; ++j) o[i][j] = 0.0f;

    for (int kb = 0; kb < SEQ / 64; ++kb) {
        const int stage = kb & 1;
        const uint32_t stg = sb + ASTG0 + stage * ASTGSZ;
        CP_WAIT(1);
        __syncthreads();

        // ---- S = Q K^T  (8 n-tiles of 8 keys) ----
        float s_acc[8][4];
#pragma unroll
        for (int j = 0; j < 8; ++j)
#pragma unroll
            for (int r = 0; r < 4; ++r) s_acc[j][r] = 0.0f;

#pragma unroll
        for (int ks = 0; ks < 4; ++ks) {
#pragma unroll
            for (int jp = 0; jp < 4; ++jp) {
                uint32_t kf[4], kl2[4];
                uint32_t a = stg + AK_HI + (uint32_t)((jp * 16 + k_r) * ASTRIDE + ks * 16 + k_c) * 2;
                LDMX4(kf, a);
                a = stg + AK_LO + (uint32_t)((jp * 16 + k_r) * ASTRIDE + ks * 16 + k_c) * 2;
                LDMX4(kl2, a);
                mma_bf16(s_acc[2 * jp],     qh[ks], kf);
                mma_bf16(s_acc[2 * jp],     qh[ks], kl2);
                mma_bf16(s_acc[2 * jp],     ql[ks], kf);
                mma_bf16(s_acc[2 * jp + 1], qh[ks], kf + 2);
                mma_bf16(s_acc[2 * jp + 1], qh[ks], kl2 + 2);
                mma_bf16(s_acc[2 * jp + 1], ql[ks], kf + 2);
            }
        }

        // ---- online softmax (rows g and g+8) ----
        float fac[2];
#pragma unroll
        for (int r = 0; r < 2; ++r) {
            float mx = -INFINITY;
#pragma unroll
            for (int j = 0; j < 8; ++j)
                mx = fmaxf(mx, fmaxf(s_acc[j][2 * r], s_acc[j][2 * r + 1]));
            mx = fmaxf(mx, __shfl_xor_sync(0xffffffffu, mx, 1));
            mx = fmaxf(mx, __shfl_xor_sync(0xffffffffu, mx, 2));
            float m_new = fmaxf(m_i[r], mx);
            fac[r] = __expf(m_i[r] - m_new);
            float sum = 0.0f;
#pragma unroll
            for (int j = 0; j < 8; ++j) {
                float e0 = __expf(s_acc[j][2 * r]     - m_new);
                float e1 = __expf(s_acc[j][2 * r + 1] - m_new);
                s_acc[j][2 * r]     = e0;
                s_acc[j][2 * r + 1] = e1;
                sum += e0 + e1;
            }
            sum += __shfl_xor_sync(0xffffffffu, sum, 1);
            sum += __shfl_xor_sync(0xffffffffu, sum, 2);
            l_i[r] = l_i[r] * fac[r] + sum;
            m_i[r] = m_new;
        }
#pragma unroll
        for (int dt = 0; dt < 8; ++dt) {
            o[dt][0] *= fac[0];
            o[dt][1] *= fac[0];
            o[dt][2] *= fac[1];
            o[dt][3] *= fac[1];
        }

        // ---- O += P V  (P split from registers; V via ldmatrix.trans) ----
#pragma unroll
        for (int kp = 0; kp < 4; ++kp) {
            uint32_t ph[4], pl[4];
            split2(s_acc[2 * kp][0],     s_acc[2 * kp][1],     ph[0], pl[0]);
            split2(s_acc[2 * kp][2],     s_acc[2 * kp][3],     ph[1], pl[1]);
            split2(s_acc[2 * kp + 1][0], s_acc[2 * kp + 1][1], ph[2], pl[2]);
            split2(s_acc[2 * kp + 1][2], s_acc[2 * kp + 1][3], ph[3], pl[3]);
#pragma unroll
            for (int dp = 0; dp < 4; ++dp) {
                uint32_t vf[4], vl2[4];
                uint32_t a = stg + AV_HI + (uint32_t)((kp * 16 + v_r) * ASTRIDE + dp * 16 + v_c) * 2;
                LDMX4T(vf, a);
                a = stg + AV_LO + (uint32_t)((kp * 16 + v_r) * ASTRIDE + dp * 16 + v_c) * 2;
                LDMX4T(vl2, a);
                mma_bf16(o[2 * dp],     ph, vf);
                mma_bf16(o[2 * dp],     pl, vf);
                mma_bf16(o[2 * dp],     ph, vl2);
                mma_bf16(o[2 * dp + 1], ph, vf + 2);
                mma_bf16(o[2 * dp + 1], pl, vf + 2);
                mma_bf16(o[2 * dp + 1], ph, vl2 + 2);
            }
        }

        __syncthreads();
        if (kb + 2 < SEQ / 64) load_kv(kb + 2, stage);
    }

    // ---- normalize + write ctx split into final-GEMM A buffers ----
    const float inv0 = 1.0f / l_i[0];
    const float inv1 = 1.0f / l_i[1];
    const int m0r = b * SEQ + qt * 128 + wid * 16 + g;
    const int m1r = m0r + 8;
#pragma unroll
    for (int nt = 0; nt < 8; ++nt) {
        int col = h * 64 + nt * 8 + qd * 2;
        uint32_t hi, lo;
        split2(o[nt][0] * inv0, o[nt][1] * inv0, hi, lo);
        *(uint32_t*)&Chi[(size_t)m0r * DMODEL + col] = hi;
        *(uint32_t*)&Clo[(size_t)m0r * DMODEL + col] = lo;
        split2(o[nt][2] * inv1, o[nt][3] * inv1, hi, lo);
        *(uint32_t*)&Chi[(size_t)m1r * DMODEL + col] = hi;
        *(uint32_t*)&Clo[(size_t)m1r * DMODEL + col] = lo;
    }
}

// ---------------------------------------------------------------------------
// Launch
// ---------------------------------------------------------------------------
extern "C" void kernel_launch(void* const* d_in, const int* in_sizes, int n_in,
                              void* d_out, int out_size)
{
    const float* q  = (const float*)d_in[0];
    const float* k  = (const float*)d_in[1];
    const float* v  = (const float*)d_in[2];
    const float* Wq = (const float*)d_in[3];
    const float* bq = (const float*)d_in[4];
    const float* Wk = (const float*)d_in[5];
    const float* bk = (const float*)d_in[6];
    const float* Wv = (const float*)d_in[7];
    const float* bv = (const float*)d_in[8];
    const float* Wo = (const float*)d_in[9];
    const float* bo = (const float*)d_in[10];
    float* out = (float*)d_out;

    __nv_bfloat16 *pAhi, *pAlo, *pWhi, *pWlo;
    __nv_bfloat16 *pQhi, *pQlo, *pKhi, *pKlo, *pVhi, *pVlo;
    cudaGetSymbolAddress((void**)&pAhi, g_Ahi);
    cudaGetSymbolAddress((void**)&pAlo, g_Alo);
    cudaGetSymbolAddress((void**)&pWhi, g_Whi);
    cudaGetSymbolAddress((void**)&pWlo, g_Wlo);
    cudaGetSymbolAddress((void**)&pQhi, g_Qhi);
    cudaGetSymbolAddress((void**)&pQlo, g_Qlo);
    cudaGetSymbolAddress((void**)&pKhi, g_Khi);
    cudaGetSymbolAddress((void**)&pKlo, g_Klo);
    cudaGetSymbolAddress((void**)&pVhi, g_Vhi);
    cudaGetSymbolAddress((void**)&pVlo, g_Vlo);

    cudaFuncSetAttribute(gemm_tc_kernel<0>, cudaFuncAttributeMaxDynamicSharedMemorySize, GSMEM);
    cudaFuncSetAttribute(gemm_tc_kernel<1>, cudaFuncAttributeMaxDynamicSharedMemorySize, GSMEM);
    cudaFuncSetAttribute(attn_mma_kernel,   cudaFuncAttributeMaxDynamicSharedMemorySize, AMMA_SMEM);

    const int nA4 = MROWS * DMODEL / 4;
    dim3 sgrid((nA4 + 255) / 256);
    dim3 tgrid(DMODEL / 32, DMODEL / 32);
    dim3 ggrid(DMODEL / 128, MROWS / 128);
    const float qscale = 0.125f;                 // 1/sqrt(64)

    // Q projection -> bf16 hi/lo heads, pre-scaled
    splitT_kernel<<<tgrid, 256>>>(Wq, pWhi, pWlo);
    split_kernel<<<sgrid, 256>>>(q, pAhi, pAlo, nA4);
    gemm_tc_kernel<1><<<ggrid, 256, GSMEM>>>(pAhi, pAlo, pWhi, pWlo, bq,
                                             nullptr, pQhi, pQlo, qscale);
    // K projection
    splitT_kernel<<<tgrid, 256>>>(Wk, pWhi, pWlo);
    split_kernel<<<sgrid, 256>>>(k, pAhi, pAlo, nA4);
    gemm_tc_kernel<1><<<ggrid, 256, GSMEM>>>(pAhi, pAlo, pWhi, pWlo, bk,
                                             nullptr, pKhi, pKlo, 1.0f);
    // V projection
    splitT_kernel<<<tgrid, 256>>>(Wv, pWhi, pWlo);
    split_kernel<<<sgrid, 256>>>(v, pAhi, pAlo, nA4);
    gemm_tc_kernel<1><<<ggrid, 256, GSMEM>>>(pAhi, pAlo, pWhi, pWlo, bv,
                                             nullptr, pVhi, pVlo, 1.0f);

    // Attention on tensor cores; writes ctx split into pAhi/pAlo
    dim3 agrid(SEQ / 128, NHEADS, BATCH);        // (16, 16, 2)
    attn_mma_kernel<<<agrid, 256, AMMA_SMEM>>>(pQhi, pQlo, pKhi, pKlo,
                                               pVhi, pVlo, pAhi, pAlo);

    // Output projection (fp32 out)
    splitT_kernel<<<tgrid, 256>>>(Wo, pWhi, pWlo);
    gemm_tc_kernel<0><<<ggrid, 256, GSMEM>>>(pAhi, pAlo, pWhi, pWlo, bo,
                                             out, nullptr, nullptr, 1.0f);
}

// round 16
// speedup vs baseline: 3.8956x; 1.0574x over previous
#include <cuda_runtime.h>
#include <cuda_bf16.h>
#include <math.h>
#include <stdint.h>

// Problem constants
#define DMODEL 1024
#define NHEADS 16
#define DK     64
#define BATCH  2
#define SEQ    2048
#define MROWS  (BATCH*SEQ)   // 4096

// ---------------------------------------------------------------------------
// Scratch (device globals; allocation is forbidden)
// ---------------------------------------------------------------------------
__device__ __nv_bfloat16 g_Ain_hi[3][MROWS*DMODEL];   // q/k/v input splits; [0] reused for ctx
__device__ __nv_bfloat16 g_Ain_lo[3][MROWS*DMODEL];
__device__ __nv_bfloat16 g_W_hi[4][DMODEL*DMODEL];    // Wq,Wk,Wv,Wo transposed splits [N,K]
__device__ __nv_bfloat16 g_W_lo[4][DMODEL*DMODEL];
__device__ __nv_bfloat16 g_Qhi[BATCH*NHEADS*SEQ*DK];  // heads layout, Q pre-scaled
__device__ __nv_bfloat16 g_Qlo[BATCH*NHEADS*SEQ*DK];
__device__ __nv_bfloat16 g_Khi[BATCH*NHEADS*SEQ*DK];
__device__ __nv_bfloat16 g_Klo[BATCH*NHEADS*SEQ*DK];
__device__ __nv_bfloat16 g_Vhi[BATCH*NHEADS*SEQ*DK];
__device__ __nv_bfloat16 g_Vlo[BATCH*NHEADS*SEQ*DK];

// ---------------------------------------------------------------------------
// Helpers
// ---------------------------------------------------------------------------
__device__ __forceinline__ uint32_t smem_u32(const void* p) {
    uint32_t a;
    asm("{ .reg .u64 t; cvta.to.shared.u64 t, %1; cvt.u32.u64 %0, t; }"
        : "=r"(a) : "l"(p));
    return a;
}
__device__ __forceinline__ void cp16s(uint32_t dst, const void* src) {
    asm volatile("cp.async.cg.shared.global [%0], [%1], 16;" :: "r"(dst), "l"(src));
}
#define CP_COMMIT() asm volatile("cp.async.commit_group;" ::: "memory")
#define CP_WAIT(n)  asm volatile("cp.async.wait_group %0;" :: "n"(n) : "memory")

__device__ __forceinline__ void mma_bf16(float* d, const uint32_t* a, const uint32_t* b) {
    asm volatile(
        "mma.sync.aligned.m16n8k16.row.col.f32.bf16.bf16.f32 "
        "{%0,%1,%2,%3}, {%4,%5,%6,%7}, {%8,%9}, {%0,%1,%2,%3};"
        : "+f"(d[0]), "+f"(d[1]), "+f"(d[2]), "+f"(d[3])
        : "r"(a[0]), "r"(a[1]), "r"(a[2]), "r"(a[3]), "r"(b[0]), "r"(b[1]));
}
#define LDMX4(r, a) \
    asm volatile("ldmatrix.sync.aligned.m8n8.x4.shared.b16 {%0,%1,%2,%3}, [%4];" \
        : "=r"((r)[0]), "=r"((r)[1]), "=r"((r)[2]), "=r"((r)[3]) : "r"(a))
#define LDMX4T(r, a) \
    asm volatile("ldmatrix.sync.aligned.m8n8.x4.trans.shared.b16 {%0,%1,%2,%3}, [%4];" \
        : "=r"((r)[0]), "=r"((r)[1]), "=r"((r)[2]), "=r"((r)[3]) : "r"(a))

__device__ __forceinline__ uint32_t pack_bf2(__nv_bfloat16 lo, __nv_bfloat16 hi) {
    return (uint32_t)__bfloat16_as_ushort(lo) | ((uint32_t)__bfloat16_as_ushort(hi) << 16);
}
// RN-based split: (x,y) -> packed hi pair + packed lo pair (used off hot path)
__device__ __forceinline__ void split2(float x, float y, uint32_t& hi, uint32_t& lo) {
    __nv_bfloat16 hx = __float2bfloat16(x);
    __nv_bfloat16 hy = __float2bfloat16(y);
    __nv_bfloat16 lx = __float2bfloat16(x - __bfloat162float(hx));
    __nv_bfloat16 ly = __float2bfloat16(y - __bfloat162float(hy));
    hi = pack_bf2(hx, hy);
    lo = pack_bf2(lx, ly);
}
// Truncation-based split: cheaper (2 LOP3 + 2 FADD + 1 packed CVT). hi is the
// truncated bf16 (exact), lo = RN(x - hi); residual <= 2^-17 |x|.
__device__ __forceinline__ void split2t(float x, float y, uint32_t& hi, uint32_t& lo) {
    uint32_t xi = __float_as_uint(x) & 0xFFFF0000u;
    uint32_t yi = __float_as_uint(y) & 0xFFFF0000u;
    hi = (xi >> 16) | yi;
    float xl = x - __uint_as_float(xi);
    float yl = y - __uint_as_float(yi);
    asm("cvt.rn.bf16x2.f32 %0, %1, %2;" : "=r"(lo) : "f"(yl), "f"(xl));  // {hi=yl, lo=xl}
}

// ---------------------------------------------------------------------------
// Fused split kernels
// ---------------------------------------------------------------------------
__global__ __launch_bounds__(256)
void splitIn_kernel(const float* __restrict__ q,
                    const float* __restrict__ k,
                    const float* __restrict__ v, int n4)
{
    const int z = blockIdx.y;
    const float* x = (z == 0) ? q : (z == 1) ? k : v;
    __nv_bfloat16* hi = g_Ain_hi[z];
    __nv_bfloat16* lo = g_Ain_lo[z];
    int i = blockIdx.x * 256 + threadIdx.x;
    if (i >= n4) return;
    float4 val = ((const float4*)x)[i];
    uint32_t h0, l0, h1, l1;
    split2(val.x, val.y, h0, l0);
    split2(val.z, val.w, h1, l1);
    ((uint2*)hi)[i] = make_uint2(h0, h1);
    ((uint2*)lo)[i] = make_uint2(l0, l1);
}

__global__ __launch_bounds__(256)
void splitT4_kernel(const float* __restrict__ W0, const float* __restrict__ W1,
                    const float* __restrict__ W2, const float* __restrict__ W3)
{
    const int z = blockIdx.z;
    const float* W = (z == 0) ? W0 : (z == 1) ? W1 : (z == 2) ? W2 : W3;
    __nv_bfloat16* hi = g_W_hi[z];
    __nv_bfloat16* lo = g_W_lo[z];

    __shared__ float t[32][33];
    const int n0 = blockIdx.x * 32, k0 = blockIdx.y * 32;
    const int tx = threadIdx.x & 31, ty = threadIdx.x >> 5;
#pragma unroll
    for (int j = 0; j < 32; j += 8)
        t[ty + j][tx] = W[(size_t)(k0 + ty + j) * DMODEL + n0 + tx];
    __syncthreads();
#pragma unroll
    for (int j = 0; j < 32; j += 8) {
        float f = t[tx][ty + j];
        __nv_bfloat16 h = __float2bfloat16(f);
        __nv_bfloat16 l = __float2bfloat16(f - __bfloat162float(h));
        size_t o = (size_t)(n0 + ty + j) * DMODEL + k0 + tx;
        hi[o] = h;
        lo[o] = l;
    }
}

// ---------------------------------------------------------------------------
// GEMM mainloop (bf16x3, ldmatrix fragments, cp.async double buffer)
// CTA tile 128x128, BK=32, 8 warps (2m x 4n), warp tile 64x32.
// ---------------------------------------------------------------------------
#define KPADB 80
#define GBUF  (128 * KPADB)
#define GSTG  (4 * GBUF)
#define G_AHI 0
#define G_ALO (1 * GBUF)
#define G_BHI (2 * GBUF)
#define G_BLO (3 * GBUF)
#define GSMEM (2 * GSTG)

__device__ __forceinline__ void gemm_mainloop(
    const __nv_bfloat16* __restrict__ Ahi, const __nv_bfloat16* __restrict__ Alo,
    const __nv_bfloat16* __restrict__ Bhi, const __nv_bfloat16* __restrict__ Blo,
    uint32_t sbase, int mbase, int nbase, float acc[4][4][4])
{
    const int tid  = threadIdx.x;
    const int wid  = tid >> 5;
    const int lane = tid & 31;
    const int warp_m = wid >> 2;
    const int warp_n = wid & 3;
    constexpr int K = DMODEL;
    constexpr int NCHUNK = K / 32;

    const int ld_row = tid >> 2;
    const int ld_g2  = tid & 3;

    auto issue_chunk = [&](int chunk, int stage) {
        uint32_t stg = sbase + stage * GSTG;
        const int k0 = chunk * 32;
#pragma unroll
        for (int it = 0; it < 2; ++it) {
            int row = ld_row + it * 64;
            size_t ga = (size_t)(mbase + row) * K + k0 + ld_g2 * 8;
            size_t gb = (size_t)(nbase + row) * K + k0 + ld_g2 * 8;
            uint32_t so = (uint32_t)(row * KPADB + ld_g2 * 16);
            cp16s(stg + G_AHI + so, Ahi + ga);
            cp16s(stg + G_ALO + so, Alo + ga);
            cp16s(stg + G_BHI + so, Bhi + gb);
            cp16s(stg + G_BLO + so, Blo + gb);
        }
        CP_COMMIT();
    };

    issue_chunk(0, 0);
    issue_chunk(1, 1);

    // ldmatrix addressing
    const int a_r  = warp_m * 64 + (lane & 15);
    const int a_cb = (lane & 16) ? 16 : 0;
    const int b_r  = warp_n * 32 + (lane & 7) + ((lane & 16) ? 8 : 0);
    const int b_cb = (lane & 8) ? 16 : 0;

    for (int ch = 0; ch < NCHUNK; ++ch) {
        const int stage = ch & 1;
        const uint32_t stg = sbase + stage * GSTG;
        CP_WAIT(1);
        __syncthreads();

#pragma unroll
        for (int kb = 0; kb < 2; ++kb) {
            const uint32_t kOff = kb * 32;
            uint32_t a_hi[4][4], a_lo[4][4];
#pragma unroll
            for (int mt = 0; mt < 4; ++mt) {
                uint32_t ad = stg + G_AHI + (uint32_t)((a_r + mt * 16) * KPADB) + kOff + a_cb;
                LDMX4(a_hi[mt], ad);
                LDMX4(a_lo[mt], ad + GBUF);
            }
            uint32_t b_hi[2][4], b_lo[2][4];
#pragma unroll
            for (int np = 0; np < 2; ++np) {
                uint32_t bd = stg + G_BHI + (uint32_t)((b_r + np * 16) * KPADB) + kOff + b_cb;
                LDMX4(b_hi[np], bd);
                LDMX4(b_lo[np], bd + GBUF);
            }
#pragma unroll
            for (int mt = 0; mt < 4; ++mt)
#pragma unroll
                for (int np = 0; np < 2; ++np)
#pragma unroll
                    for (int hf = 0; hf < 2; ++hf) {
                        float* d = acc[mt][2 * np + hf];
                        mma_bf16(d, a_hi[mt], b_hi[np] + 2 * hf);
                        mma_bf16(d, a_hi[mt], b_lo[np] + 2 * hf);
                        mma_bf16(d, a_lo[mt], b_hi[np] + 2 * hf);
                    }
        }

        __syncthreads();
        if (ch + 2 < NCHUNK) issue_chunk(ch + 2, stage);
    }
}

// Fused QKV projections: grid.z selects {q,k,v}. Emits bf16 hi/lo head layout.
__global__ __launch_bounds__(256)
void gemm_qkv_kernel(const float* __restrict__ bq,
                     const float* __restrict__ bk,
                     const float* __restrict__ bv)
{
    extern __shared__ char sm[];
    const uint32_t sbase = smem_u32(sm);
    const int z = blockIdx.z;
    const __nv_bfloat16* Ahi = g_Ain_hi[z];
    const __nv_bfloat16* Alo = g_Ain_lo[z];
    const __nv_bfloat16* Bhi = g_W_hi[z];
    const __nv_bfloat16* Blo = g_W_lo[z];
    const float* bias = (z == 0) ? bq : (z == 1) ? bk : bv;
    __nv_bfloat16* Ohi = (z == 0) ? g_Qhi : (z == 1) ? g_Khi : g_Vhi;
    __nv_bfloat16* Olo = (z == 0) ? g_Qlo : (z == 1) ? g_Klo : g_Vlo;
    const float scale = (z == 0) ? 0.125f : 1.0f;   // 1/sqrt(64) on Q

    const int nbase = blockIdx.x * 128;
    const int mbase = blockIdx.y * 128;

    float acc[4][4][4];
#pragma unroll
    for (int i = 0; i < 4; ++i)
#pragma unroll
        for (int j = 0; j < 4; ++j)
#pragma unroll
            for (int r = 0; r < 4; ++r) acc[i][j][r] = 0.0f;

    gemm_mainloop(Ahi, Alo, Bhi, Blo, sbase, mbase, nbase, acc);

    const int lane = threadIdx.x & 31;
    const int wid  = threadIdx.x >> 5;
    const int g  = lane >> 2;
    const int tq = lane & 3;
    const int warp_m = wid >> 2;
    const int warp_n = wid & 3;
#pragma unroll
    for (int mt = 0; mt < 4; ++mt)
#pragma unroll
        for (int half = 0; half < 2; ++half) {
            int m = mbase + warp_m * 64 + mt * 16 + g + half * 8;
#pragma unroll
            for (int nt = 0; nt < 4; ++nt) {
                int n = nbase + warp_n * 32 + nt * 8 + tq * 2;
                float ox = (acc[mt][nt][half * 2 + 0] + bias[n + 0]) * scale;
                float oy = (acc[mt][nt][half * 2 + 1] + bias[n + 1]) * scale;
                int b = m >> 11, s = m & 2047;
                int hh = n >> 6, d = n & 63;
                size_t idx = (((size_t)(b * NHEADS + hh)) * SEQ + s) * DK + d;
                uint32_t hi, lo;
                split2(ox, oy, hi, lo);
                *(uint32_t*)&Ohi[idx] = hi;
                *(uint32_t*)&Olo[idx] = lo;
            }
        }
}

// Output projection: ctx split (in g_Ain[0]) x Wo -> fp32 out
__global__ __launch_bounds__(256)
void gemm_out_kernel(const float* __restrict__ bo, float* __restrict__ C)
{
    extern __shared__ char sm[];
    const uint32_t sbase = smem_u32(sm);
    const int nbase = blockIdx.x * 128;
    const int mbase = blockIdx.y * 128;

    float acc[4][4][4];
#pragma unroll
    for (int i = 0; i < 4; ++i)
#pragma unroll
        for (int j = 0; j < 4; ++j)
#pragma unroll
            for (int r = 0; r < 4; ++r) acc[i][j][r] = 0.0f;

    gemm_mainloop(g_Ain_hi[0], g_Ain_lo[0], g_W_hi[3], g_W_lo[3],
                  sbase, mbase, nbase, acc);

    const int lane = threadIdx.x & 31;
    const int wid  = threadIdx.x >> 5;
    const int g  = lane >> 2;
    const int tq = lane & 3;
    const int warp_m = wid >> 2;
    const int warp_n = wid & 3;
#pragma unroll
    for (int mt = 0; mt < 4; ++mt)
#pragma unroll
        for (int half = 0; half < 2; ++half) {
            int m = mbase + warp_m * 64 + mt * 16 + g + half * 8;
#pragma unroll
            for (int nt = 0; nt < 4; ++nt) {
                int n = nbase + warp_n * 32 + nt * 8 + tq * 2;
                float2 o;
                o.x = acc[mt][nt][half * 2 + 0] + bo[n + 0];
                o.y = acc[mt][nt][half * 2 + 1] + bo[n + 1];
                *(float2*)&C[(size_t)m * DMODEL + n] = o;
            }
        }
}

// ---------------------------------------------------------------------------
// Flash attention on mma.sync (bf16x3).  CTA = 128 q-rows x 64-key blocks.
// 8 warps x 16 q-rows.  Ctx split written into g_Ain[0] for the final GEMM.
// ---------------------------------------------------------------------------
#define ASTRIDE 72
#define AQ_HI   0
#define AQ_LO   18432
#define ASTG0   36864
#define ASTGSZ  36864
#define AK_HI   0
#define AK_LO   9216
#define AV_HI   18432
#define AV_LO   27648
#define AMMA_SMEM (ASTG0 + 2 * ASTGSZ)

__global__ __launch_bounds__(256)
void attn_mma_kernel()
{
    extern __shared__ char smc[];
    const uint32_t sb = smem_u32(smc);

    const int tid = threadIdx.x;
    const int wid = tid >> 5;
    const int lane = tid & 31;
    const int g  = lane >> 2;
    const int qd = lane & 3;
    const int qt = blockIdx.x;
    const int h  = blockIdx.y;
    const int b  = blockIdx.z;

    const size_t bh = (size_t)(b * NHEADS + h) * SEQ;
    const __nv_bfloat16* Qh_g = g_Qhi + (bh + (size_t)qt * 128) * DK;
    const __nv_bfloat16* Ql_g = g_Qlo + (bh + (size_t)qt * 128) * DK;
    const __nv_bfloat16* Kh_g = g_Khi + bh * DK;
    const __nv_bfloat16* Kl_g = g_Klo + bh * DK;
    const __nv_bfloat16* Vh_g = g_Vhi + bh * DK;
    const __nv_bfloat16* Vl_g = g_Vlo + bh * DK;

    // Q stage (once)
#pragma unroll
    for (int it = 0; it < 4; ++it) {
        int idx = tid + it * 256;
        int row = idx >> 3;
        int gg  = idx & 7;
        uint32_t off = (uint32_t)(row * ASTRIDE + gg * 8) * 2;
        cp16s(sb + AQ_HI + off, Qh_g + row * DK + gg * 8);
        cp16s(sb + AQ_LO + off, Ql_g + row * DK + gg * 8);
    }
    CP_COMMIT();

    auto load_kv = [&](int blk, int s) {
        uint32_t stg = sb + ASTG0 + s * ASTGSZ;
        const __nv_bfloat16* kh = Kh_g + (size_t)blk * 64 * DK;
        const __nv_bfloat16* kl = Kl_g + (size_t)blk * 64 * DK;
        const __nv_bfloat16* vh = Vh_g + (size_t)blk * 64 * DK;
        const __nv_bfloat16* vl = Vl_g + (size_t)blk * 64 * DK;
#pragma unroll
        for (int it = 0; it < 2; ++it) {
            int idx = tid + it * 256;
            int row = idx >> 3;
            int gg  = idx & 7;
            uint32_t off = (uint32_t)(row * ASTRIDE + gg * 8) * 2;
            const int go = row * DK + gg * 8;
            cp16s(stg + AK_HI + off, kh + go);
            cp16s(stg + AK_LO + off, kl + go);
            cp16s(stg + AV_HI + off, vh + go);
            cp16s(stg + AV_LO + off, vl + go);
        }
        CP_COMMIT();
    };

    load_kv(0, 0);
    load_kv(1, 1);

    const int q_r = lane & 15;
    const int q_c = (lane & 16) ? 8 : 0;
    const int k_r = (lane & 7) + ((lane & 16) ? 8 : 0);
    const int k_c = (lane & 8) ? 8 : 0;
    const int v_r = (lane & 7) + ((lane & 8) ? 8 : 0);
    const int v_c = (lane & 16) ? 8 : 0;

    CP_WAIT(2);
    __syncthreads();

    uint32_t qh[4][4], ql[4][4];
    const int qrow0 = wid * 16;
#pragma unroll
    for (int ks = 0; ks < 4; ++ks) {
        uint32_t a = sb + AQ_HI + (uint32_t)((qrow0 + q_r) * ASTRIDE + ks * 16 + q_c) * 2;
        LDMX4(qh[ks], a);
        a = sb + AQ_LO + (uint32_t)((qrow0 + q_r) * ASTRIDE + ks * 16 + q_c) * 2;
        LDMX4(ql[ks], a);
    }

    float m_i[2] = {-INFINITY, -INFINITY};
    float l_i[2] = {0.0f, 0.0f};
    float o[8][4];
#pragma unroll
    for (int i = 0; i < 8; ++i)
#pragma unroll
        for (int j = 0; j < 4; ++j) o[i][j] = 0.0f;

    for (int kb = 0; kb < SEQ / 64; ++kb) {
        const int stage = kb & 1;
        const uint32_t stg = sb + ASTG0 + stage * ASTGSZ;
        CP_WAIT(1);
        __syncthreads();

        // S = Q K^T
        float s_acc[8][4];
#pragma unroll
        for (int j = 0; j < 8; ++j)
#pragma unroll
            for (int r = 0; r < 4; ++r) s_acc[j][r] = 0.0f;

#pragma unroll
        for (int ks = 0; ks < 4; ++ks) {
#pragma unroll
            for (int jp = 0; jp < 4; ++jp) {
                uint32_t kf[4], kl2[4];
                uint32_t a = stg + AK_HI + (uint32_t)((jp * 16 + k_r) * ASTRIDE + ks * 16 + k_c) * 2;
                LDMX4(kf, a);
                a = stg + AK_LO + (uint32_t)((jp * 16 + k_r) * ASTRIDE + ks * 16 + k_c) * 2;
                LDMX4(kl2, a);
                mma_bf16(s_acc[2 * jp],     qh[ks], kf);
                mma_bf16(s_acc[2 * jp],     qh[ks], kl2);
                mma_bf16(s_acc[2 * jp],     ql[ks], kf);
                mma_bf16(s_acc[2 * jp + 1], qh[ks], kf + 2);
                mma_bf16(s_acc[2 * jp + 1], qh[ks], kl2 + 2);
                mma_bf16(s_acc[2 * jp + 1], ql[ks], kf + 2);
            }
        }

        // online softmax (rows g and g+8)
        float fac[2];
#pragma unroll
        for (int r = 0; r < 2; ++r) {
            float mx = -INFINITY;
#pragma unroll
            for (int j = 0; j < 8; ++j)
                mx = fmaxf(mx, fmaxf(s_acc[j][2 * r], s_acc[j][2 * r + 1]));
            mx = fmaxf(mx, __shfl_xor_sync(0xffffffffu, mx, 1));
            mx = fmaxf(mx, __shfl_xor_sync(0xffffffffu, mx, 2));
            float m_new = fmaxf(m_i[r], mx);
            fac[r] = __expf(m_i[r] - m_new);
            float sum = 0.0f;
#pragma unroll
            for (int j = 0; j < 8; ++j) {
                float e0 = __expf(s_acc[j][2 * r]     - m_new);
                float e1 = __expf(s_acc[j][2 * r + 1] - m_new);
                s_acc[j][2 * r]     = e0;
                s_acc[j][2 * r + 1] = e1;
                sum += e0 + e1;
            }
            sum += __shfl_xor_sync(0xffffffffu, sum, 1);
            sum += __shfl_xor_sync(0xffffffffu, sum, 2);
            l_i[r] = l_i[r] * fac[r] + sum;
            m_i[r] = m_new;
        }
#pragma unroll
        for (int dt = 0; dt < 8; ++dt) {
            o[dt][0] *= fac[0];
            o[dt][1] *= fac[0];
            o[dt][2] *= fac[1];
            o[dt][3] *= fac[1];
        }

        // O += P V   (P trunc-split in registers)
#pragma unroll
        for (int kp = 0; kp < 4; ++kp) {
            uint32_t ph[4], pl[4];
            split2t(s_acc[2 * kp][0],     s_acc[2 * kp][1],     ph[0], pl[0]);
            split2t(s_acc[2 * kp][2],     s_acc[2 * kp][3],     ph[1], pl[1]);
            split2t(s_acc[2 * kp + 1][0], s_acc[2 * kp + 1][1], ph[2], pl[2]);
            split2t(s_acc[2 * kp + 1][2], s_acc[2 * kp + 1][3], ph[3], pl[3]);
#pragma unroll
            for (int dp = 0; dp < 4; ++dp) {
                uint32_t vf[4], vl2[4];
                uint32_t a = stg + AV_HI + (uint32_t)((kp * 16 + v_r) * ASTRIDE + dp * 16 + v_c) * 2;
                LDMX4T(vf, a);
                a = stg + AV_LO + (uint32_t)((kp * 16 + v_r) * ASTRIDE + dp * 16 + v_c) * 2;
                LDMX4T(vl2, a);
                mma_bf16(o[2 * dp],     ph, vf);
                mma_bf16(o[2 * dp],     pl, vf);
                mma_bf16(o[2 * dp],     ph, vl2);
                mma_bf16(o[2 * dp + 1], ph, vf + 2);
                mma_bf16(o[2 * dp + 1], pl, vf + 2);
                mma_bf16(o[2 * dp + 1], ph, vl2 + 2);
            }
        }

        __syncthreads();
        if (kb + 2 < SEQ / 64) load_kv(kb + 2, stage);
    }

    // normalize + write ctx split into final-GEMM A buffers
    __nv_bfloat16* Chi = g_Ain_hi[0];
    __nv_bfloat16* Clo = g_Ain_lo[0];
    const float inv0 = 1.0f / l_i[0];
    const float inv1 = 1.0f / l_i[1];
    const int m0r = b * SEQ + qt * 128 + wid * 16 + g;
    const int m1r = m0r + 8;
#pragma unroll
    for (int nt = 0; nt < 8; ++nt) {
        int col = h * 64 + nt * 8 + qd * 2;
        uint32_t hi, lo;
        split2(o[nt][0] * inv0, o[nt][1] * inv0, hi, lo);
        *(uint32_t*)&Chi[(size_t)m0r * DMODEL + col] = hi;
        *(uint32_t*)&Clo[(size_t)m0r * DMODEL + col] = lo;
        split2(o[nt][2] * inv1, o[nt][3] * inv1, hi, lo);
        *(uint32_t*)&Chi[(size_t)m1r * DMODEL + col] = hi;
        *(uint32_t*)&Clo[(size_t)m1r * DMODEL + col] = lo;
    }
}

// ---------------------------------------------------------------------------
// Launch
// ---------------------------------------------------------------------------
extern "C" void kernel_launch(void* const* d_in, const int* in_sizes, int n_in,
                              void* d_out, int out_size)
{
    const float* q  = (const float*)d_in[0];
    const float* k  = (const float*)d_in[1];
    const float* v  = (const float*)d_in[2];
    const float* Wq = (const float*)d_in[3];
    const float* bq = (const float*)d_in[4];
    const float* Wk = (const float*)d_in[5];
    const float* bk = (const float*)d_in[6];
    const float* Wv = (const float*)d_in[7];
    const float* bv = (const float*)d_in[8];
    const float* Wo = (const float*)d_in[9];
    const float* bo = (const float*)d_in[10];
    float* out = (float*)d_out;

    cudaFuncSetAttribute(gemm_qkv_kernel, cudaFuncAttributeMaxDynamicSharedMemorySize, GSMEM);
    cudaFuncSetAttribute(gemm_out_kernel, cudaFuncAttributeMaxDynamicSharedMemorySize, GSMEM);
    cudaFuncSetAttribute(attn_mma_kernel, cudaFuncAttributeMaxDynamicSharedMemorySize, AMMA_SMEM);

    const int nA4 = MROWS * DMODEL / 4;

    // 1. all weight splits (one launch)
    dim3 tgrid(DMODEL / 32, DMODEL / 32, 4);
    splitT4_kernel<<<tgrid, 256>>>(Wq, Wk, Wv, Wo);

    // 2. all input splits (one launch)
    dim3 sgrid((nA4 + 255) / 256, 3);
    splitIn_kernel<<<sgrid, 256>>>(q, k, v, nA4);

    // 3. fused QKV projections
    dim3 ggrid3(DMODEL / 128, MROWS / 128, 3);   // (8, 32, 3) = 768 CTAs
    gemm_qkv_kernel<<<ggrid3, 256, GSMEM>>>(bq, bk, bv);

    // 4. attention (tensor-core); writes ctx split into g_Ain[0]
    dim3 agrid(SEQ / 128, NHEADS, BATCH);        // (16, 16, 2)
    attn_mma_kernel<<<agrid, 256, AMMA_SMEM>>>();

    // 5. output projection
    dim3 ggrid(DMODEL / 128, MROWS / 128);       // (8, 32)
    gemm_out_kernel<<<ggrid, 256, GSMEM>>>(bo, out);
}